// round 16
// baseline (speedup 1.0000x reference)
#include <cuda_runtime.h>
#include <cuda_pipeline.h>
#include <cuda_bf16.h>

// ROI align 2.5D — separable weights + cp.async SMEM-staged deep prefetch.
// fea: (B=16, C=64, H=128, W=128, D=8) f32. keypoints: (16,5,3) f32.
// out: (16, 5, 64, 2, 2, 8) f32.
//
// out[n,c,ph,pw,d] = (1/(gh*gw)) * sum_y Wy[y] * sum_x Wx[x] * fea[b,c,y,x,d]
//
// R16: the register file capped bytes-in-flight (~8 LDG.128/thread max at
// usable occupancy). cp.async (LDGSTS) stages into SMEM with ZERO register
// cost and no depth cap: each 128-thread block issues its ENTIRE window
// (<=40 x 16B copies/thread) up front, builds the weight vectors during the
// flight, then waits once and consumes at LDS speed. 2 resident blocks/SM
// (80KB dynamic smem each) keep ~160KB in flight per SM.

#define RB  16
#define RC  64
#define RH  128
#define RW  128
#define NKP 5
#define NROI (RB * NKP)          // 80
#define CROP 16.0f               // H * 1/8
#define WSLOTS 32                // zero-padded weight slots
#define MAXROWS 20               // padded staged rows (ny<=18 -> pad<=20)
#define TPB 128                  // 4 warps = 4 channels per block
#define SMEM_DYN (2 * MAXROWS * TPB * 16)   // 81920 B

__global__ __launch_bounds__(TPB)
void roi_align_25d_kernel(const float* __restrict__ fea,
                          const float* __restrict__ kp,
                          float* __restrict__ out) {
    extern __shared__ float4 stage[];            // [2][MAXROWS][TPB]
    float4* __restrict__ st1 = stage;
    float4* __restrict__ st2 = stage + MAXROWS * TPB;
    __shared__ float Wx[WSLOTS], Wy[WSLOTS];

    const int blk = blockIdx.x;          // 5120 blocks: ROI x bin x cg
    const int cg  = blk & 15;            // channel group (4 ch)
    const int bin = (blk >> 4) & 3;      // ph*2 + pw
    const int n   = blk >> 6;            // ROI index 0..79
    const int ph  = bin >> 1;
    const int pw  = bin & 1;
    const int b   = n / NKP;

    const int t    = threadIdx.x;
    const int wid  = t >> 5;
    const int lane = t & 31;
    const int x    = lane >> 1;          // x-pixel within window, 0..15
    const int dq   = lane & 1;           // which float4 of the 8-float depth
    const int c    = cg * 4 + wid;       // channel of this warp

    // ---- per-thread window geometry (no loop, no sync): x axis ----
    const float kx = kp[n * 3 + 0] * 128.0f;
    const float mnx = fminf(fmaxf(kx - CROP, 0.0f), 127.0f);
    const float mxx = fminf(fmaxf(kx + CROP, 0.0f), 127.0f);
    const float roix = fmaxf(mxx - mnx, 1.0f);
    const float bsx  = roix * 0.5f;
    const int   gx   = (int)ceilf(bsx);              // 1..16
    const float stepx = bsx / (float)gx;
    const float startx = mnx + (float)pw * bsx;
    float s0x = startx + 0.5f * stepx;
    int x0 = (int)floorf(fmaxf(s0x, 0.0f)); if (x0 > 127) x0 = 127;
    float slx = startx + ((float)(gx - 1) + 0.5f) * stepx;  // last sample
    int l0x = (int)floorf(fmaxf(slx, 0.0f));
    const int hix = (l0x >= 127) ? 127 : (l0x + 1);
    const int nx  = hix - x0 + 1;                    // <= 18

    // ---- y axis ----
    const float ky = kp[n * 3 + 1] * 128.0f;
    const float mny = fminf(fmaxf(ky - CROP, 0.0f), 127.0f);
    const float mxy = fminf(fmaxf(ky + CROP, 0.0f), 127.0f);
    const float roiy = fmaxf(mxy - mny, 1.0f);
    const float bsy  = roiy * 0.5f;
    const int   gy   = (int)ceilf(bsy);
    const float stepy = bsy / (float)gy;
    const float starty = mny + (float)ph * bsy;
    float s0y = starty + 0.5f * stepy;
    int y0 = (int)floorf(fmaxf(s0y, 0.0f)); if (y0 > 127) y0 = 127;
    float sly = starty + ((float)(gy - 1) + 0.5f) * stepy;
    int l0y = (int)floorf(fmaxf(sly, 0.0f));
    const int hiy = (l0y >= 127) ? 127 : (l0y + 1);
    const int ny  = hiy - y0 + 1;                    // <= 18

    const float inv = 1.0f / ((float)(gx * gy));
    const int nyM1  = ny - 1;
    const int nyPad = (ny + 3) & ~3;                 // <= 20

    // ---- addresses ----
    const float4* __restrict__ fp = (const float4*)fea;
    const int rowS  = RW * 2;
    const int base4 = (((b * RC + c) * RH + y0) * RW + x0) * 2 + dq;
    const int idx1  = base4 + x * 2;
    const int idx2  = base4 + (x + 16) * 2;
    const bool act1 = (x < nx);
    const bool tail = (x + 16 < nx);
    const bool wide = (nx > 16);                     // block-uniform

    const float4 z4 = make_float4(0.f, 0.f, 0.f, 0.f);

    // zero-fill slots that no copy will write (weight is 0; avoid NaN*0)
    if (!act1)          for (int r = 0; r < nyPad; r++) st1[r * TPB + t] = z4;
    if (wide && !tail)  for (int r = 0; r < nyPad; r++) st2[r * TPB + t] = z4;

    // ---- issue ALL copies up front (register-free in-flight) ----
    for (int r = 0; r < nyPad; r++) {
        const int rc = min(r, nyM1);                 // padded rows = dups, Wy=0
        if (act1) __pipeline_memcpy_async(&st1[r * TPB + t], fp + idx1 + rc * rowS, 16);
        if (tail) __pipeline_memcpy_async(&st2[r * TPB + t], fp + idx2 + rc * rowS, 16);
    }
    __pipeline_commit();

    // ---- weight vectors built DURING the async flight ----
    if (t < 2) {
        const float start = t ? starty : startx;
        const float step  = t ? stepy  : stepx;
        const int   g     = t ? gy     : gx;
        const int   base  = t ? y0     : x0;
        float* Wp = t ? Wy : Wx;
        #pragma unroll
        for (int i = 0; i < WSLOTS; i++) Wp[i] = 0.0f;
        for (int gi = 0; gi < g; gi++) {
            float s = start + ((float)gi + 0.5f) * step;
            if (s < -1.0f || s > 128.0f) continue;   // validity mask
            float c0 = fmaxf(s, 0.0f);
            int l0 = (int)floorf(c0);
            int lo, hi; float fr;
            if (l0 >= 127) { lo = 127; hi = 127; fr = 0.0f; }
            else           { lo = l0;  hi = l0 + 1; fr = c0 - (float)l0; }
            Wp[lo - base] += 1.0f - fr;
            Wp[hi - base] += fr;
        }
    }
    __syncthreads();
    __pipeline_wait_prior(0);

    // ---- consume from SMEM ----
    float4 acc1 = z4, acc2 = z4;
    if (!wide) {
        for (int r = 0; r < nyPad; r++) {
            const float wy = Wy[r];
            const float4 v = st1[r * TPB + t];
            acc1.x += wy * v.x;  acc1.y += wy * v.y;
            acc1.z += wy * v.z;  acc1.w += wy * v.w;
        }
    } else {
        for (int r = 0; r < nyPad; r++) {
            const float wy = Wy[r];
            const float4 v1 = st1[r * TPB + t];
            const float4 v2 = st2[r * TPB + t];
            acc1.x += wy * v1.x;  acc1.y += wy * v1.y;
            acc1.z += wy * v1.z;  acc1.w += wy * v1.w;
            acc2.x += wy * v2.x;  acc2.y += wy * v2.y;
            acc2.z += wy * v2.z;  acc2.w += wy * v2.w;
        }
    }

    const float wx1 = Wx[x];
    const float wx2 = Wx[x + 16];                    // zero-padded -> safe
    float4 s;
    s.x = wx1 * acc1.x + wx2 * acc2.x;
    s.y = wx1 * acc1.y + wx2 * acc2.y;
    s.z = wx1 * acc1.z + wx2 * acc2.z;
    s.w = wx1 * acc1.w + wx2 * acc2.w;

    // Reduce over x (lane bits 1..4), keeping dq pairs separate.
    #pragma unroll
    for (int m = 2; m <= 16; m <<= 1) {
        s.x += __shfl_xor_sync(0xffffffffu, s.x, m);
        s.y += __shfl_xor_sync(0xffffffffu, s.y, m);
        s.z += __shfl_xor_sync(0xffffffffu, s.z, m);
        s.w += __shfl_xor_sync(0xffffffffu, s.w, m);
    }

    if (lane < 2) {
        s.x *= inv; s.y *= inv; s.z *= inv; s.w *= inv;
        // out: (NROI, C, 2, 2, 8) -> float4 index (((n*C+c)*2+ph)*2+pw)*2+dq
        float4* __restrict__ op = (float4*)out;
        op[(((n * RC + c) * 2 + ph) * 2 + pw) * 2 + dq] = s;
    }
}

extern "C" void kernel_launch(void* const* d_in, const int* in_sizes, int n_in,
                              void* d_out, int out_size) {
    const float* fea = (const float*)d_in[0];
    const float* kp  = (const float*)d_in[1];
    float* out = (float*)d_out;
    (void)in_sizes; (void)n_in; (void)out_size;

    cudaFuncSetAttribute(roi_align_25d_kernel,
                         cudaFuncAttributeMaxDynamicSharedMemorySize, SMEM_DYN);

    dim3 grid(NROI * 4 * 16);   // 5120 blocks: ROI x bin x 4-channel group
    dim3 block(TPB);            // 4 warps = 4 channels
    roi_align_25d_kernel<<<grid, block, SMEM_DYN>>>(fea, kp, out);
}

// round 17
// speedup vs baseline: 1.8404x; 1.8404x over previous
#include <cuda_runtime.h>
#include <cuda_bf16.h>

// ROI align 2.5D — separable-weight formulation.
// fea: (B=16, C=64, H=128, W=128, D=8) f32, contiguous.
// keypoints: (16, 5, 3) f32.
// out: (16, 5, 64, 2, 2, 8) f32.
//
// Per (ROI, bin): out[c,d] = (1/(gh*gw)) * sum_y Wy[y] * sum_x Wx[x] * fea[b,c,y,x,d]
//
// R17 = R15 (warp-per-channel, 512B spans, register load-batches) with the
// y-loop trip count fixed at a COMPILE-TIME 20 and fully unrolled: rows past
// ny are clamped dups (L1 hits, Wy=0). A branch-free fixed-length body lets
// ptxas software-pipeline the LDG.128 stream to the register budget —
// sustained ~10 loads in flight instead of 8-then-drain bursts.

#define RB  16
#define RC  64
#define RH  128
#define RW  128
#define RD  8
#define NKP 5
#define NROI (RB * NKP)          // 80
#define CROP 16.0f               // H * 1/8
#define WSLOTS 32                // zero-padded: Wy[r>=ny]=0, Wx[x+16]=0 safe
#define WPB 8                    // warps (channels) per block
#define NYFIX 20                 // fixed unrolled row count (ny <= 18)

__global__ __launch_bounds__(256, 4)
void roi_align_25d_kernel(const float* __restrict__ fea,
                          const float* __restrict__ kp,
                          float* __restrict__ out) {
    const int blk = blockIdx.x;          // 2560 blocks: ROI x bin x cg
    const int cg  = blk & 7;             // channel group (8 ch)
    const int bin = (blk >> 3) & 3;      // ph*2 + pw
    const int n   = blk >> 5;            // ROI index 0..79
    const int ph  = bin >> 1;
    const int pw  = bin & 1;
    const int b   = n / NKP;

    __shared__ float Wx[WSLOTS], Wy[WSLOTS];
    __shared__ int   sBase[2];   // [0]=x0, [1]=y0
    __shared__ int   sCnt[2];    // [0]=nx, [1]=ny
    __shared__ int   sG[2];      // [0]=gw, [1]=gh

    const int t    = threadIdx.x;
    const int wid  = t >> 5;
    const int lane = t & 31;

    if (t < 2) {
        // t==0 -> x axis (uses pw), t==1 -> y axis (uses ph)
        float coord = kp[n * 3 + t] * 128.0f;
        float mn = fminf(fmaxf(coord - CROP, 0.0f), 127.0f);
        float mx = fminf(fmaxf(coord + CROP, 0.0f), 127.0f);
        float roi = fmaxf(mx - mn, 1.0f);
        float bin_sz = roi * 0.5f;                 // roi / P (P=2)
        int   g = (int)ceilf(bin_sz);              // ceil(roi/2), 1..16
        float step = bin_sz / (float)g;
        int   p = (t == 0) ? pw : ph;
        float start = mn + (float)p * bin_sz;

        float* Wp = (t == 0) ? Wx : Wy;
        #pragma unroll
        for (int i = 0; i < WSLOTS; i++) Wp[i] = 0.0f;

        // first sample defines the base index (samples are monotone in g)
        float s0 = start + 0.5f * step;
        int base = (int)floorf(fmaxf(s0, 0.0f));
        if (base > 127) base = 127;
        int maxc = base;

        for (int gi = 0; gi < g; gi++) {
            float s = start + ((float)gi + 0.5f) * step;
            if (s < -1.0f || s > 128.0f) continue;     // validity mask
            float c0 = fmaxf(s, 0.0f);
            int l0 = (int)floorf(c0);
            int lo, hi; float fr;
            if (l0 >= 127) { lo = 127; hi = 127; fr = 0.0f; }
            else           { lo = l0;  hi = l0 + 1; fr = c0 - (float)l0; }
            Wp[lo - base] += 1.0f - fr;
            Wp[hi - base] += fr;
            if (hi > maxc) maxc = hi;
        }
        sBase[t] = base;
        sCnt[t]  = maxc - base + 1;
        sG[t]    = g;
    }
    __syncthreads();

    const int x0 = sBase[0], nx = sCnt[0];
    const int y0 = sBase[1], ny = sCnt[1];
    const float inv = 1.0f / ((float)sG[0] * (float)sG[1]);

    const int c  = cg * WPB + wid;       // channel of this warp
    const int x  = lane >> 1;            // x-pixel within window, 0..15
    const int dq = lane & 1;             // which float4 of the 8-float depth

    const float4* __restrict__ fp = (const float4*)fea;

    // Per-lane weights; clamp OOW lanes to x=0 (weight is 0, load is L1 dup).
    const float wx1 = Wx[x];
    const int   xe1 = (x < nx) ? x : 0;
    const float wx2 = Wx[x + 16];                 // zero-padded -> safe
    const int   xe2 = (x + 16 < nx) ? x + 16 : 0;

    // float4 index: (((b*C + c)*H + y)*W + x)*2 + dq   (max ~33.5M, fits int)
    const int rowStride = RW * 2;
    const int idx1 = (((b * RC + c) * RH + y0) * RW + x0 + xe1) * 2 + dq;
    const int idx2 = (((b * RC + c) * RH + y0) * RW + x0 + xe2) * 2 + dq;

    float4 acc1 = make_float4(0.f, 0.f, 0.f, 0.f);
    float4 acc2 = make_float4(0.f, 0.f, 0.f, 0.f);

    const int nyM1 = ny - 1;

    if (nx <= 16) {
        // Fixed 20-row fully-unrolled stream: ptxas pipelines the LDGs.
        // Rows past ny are clamped dups (L1 hits); Wy is zero there.
        #pragma unroll
        for (int r = 0; r < NYFIX; r++) {
            const int iyc = min(r, nyM1);
            const float4 v = fp[idx1 + iyc * rowStride];
            const float wy = Wy[r];
            acc1.x += wy * v.x;  acc1.y += wy * v.y;
            acc1.z += wy * v.z;  acc1.w += wy * v.w;
        }
    } else {
        #pragma unroll
        for (int r = 0; r < NYFIX; r++) {
            const int iyc = min(r, nyM1);
            const float4 v1 = fp[idx1 + iyc * rowStride];
            const float4 v2 = fp[idx2 + iyc * rowStride];
            const float wy = Wy[r];
            acc1.x += wy * v1.x;  acc1.y += wy * v1.y;
            acc1.z += wy * v1.z;  acc1.w += wy * v1.w;
            acc2.x += wy * v2.x;  acc2.y += wy * v2.y;
            acc2.z += wy * v2.z;  acc2.w += wy * v2.w;
        }
    }

    float4 s;
    s.x = wx1 * acc1.x + wx2 * acc2.x;
    s.y = wx1 * acc1.y + wx2 * acc2.y;
    s.z = wx1 * acc1.z + wx2 * acc2.z;
    s.w = wx1 * acc1.w + wx2 * acc2.w;

    // Reduce over x (lane bits 1..4), keeping dq pairs separate.
    #pragma unroll
    for (int m = 2; m <= 16; m <<= 1) {
        s.x += __shfl_xor_sync(0xffffffffu, s.x, m);
        s.y += __shfl_xor_sync(0xffffffffu, s.y, m);
        s.z += __shfl_xor_sync(0xffffffffu, s.z, m);
        s.w += __shfl_xor_sync(0xffffffffu, s.w, m);
    }

    if (lane < 2) {
        s.x *= inv; s.y *= inv; s.z *= inv; s.w *= inv;
        // out: (NROI, C, 2, 2, 8) -> float4 index (((n*C+c)*2+ph)*2+pw)*2+dq
        float4* __restrict__ op = (float4*)out;
        op[(((n * RC + c) * 2 + ph) * 2 + pw) * 2 + dq] = s;
    }
}

extern "C" void kernel_launch(void* const* d_in, const int* in_sizes, int n_in,
                              void* d_out, int out_size) {
    const float* fea = (const float*)d_in[0];
    const float* kp  = (const float*)d_in[1];
    float* out = (float*)d_out;
    (void)in_sizes; (void)n_in; (void)out_size;

    dim3 grid(NROI * 4 * (RC / WPB));   // 2560 blocks: ROI x bin x channel-group
    dim3 block(32 * WPB);               // 8 warps = 8 channels
    roi_align_25d_kernel<<<grid, block>>>(fea, kp, out);
}